// round 8
// baseline (speedup 1.0000x reference)
#include <cuda_runtime.h>
#include <cuda_bf16.h>
#include <cuda_fp16.h>
#include <math.h>
#include <stdint.h>

#define BATCH 4
#define CH    256
#define NTOK  4096
#define INTER 32
// QK scale with log2(e) folded in: scores come out in log2 units -> exp2
#define QSC (0.17677669529663687f * 1.4426950408889634f)

// Scratch (no allocation allowed)
__device__ __nv_bfloat16 g_q[(size_t)BATCH * NTOK * INTER];
__device__ __nv_bfloat16 g_k[(size_t)BATCH * NTOK * INTER];
__device__ __half        g_v[(size_t)BATCH * NTOK * CH];
__device__ __nv_bfloat16 g_wt[320 * 256];   // fused [Wq;Wk;Wv], q rows pre-scaled
__device__ float         g_bias[320];       // fused biases, q part pre-scaled

// ---------------------------------------------------------------------------
// ptx helpers
// ---------------------------------------------------------------------------
__device__ __forceinline__ uint32_t smem_u32(const void* p) {
    return (uint32_t)__cvta_generic_to_shared(p);
}
__device__ __forceinline__ void cp16(uint32_t dst, const void* src) {
    asm volatile("cp.async.cg.shared.global [%0], [%1], 16;" :: "r"(dst), "l"(src));
}
__device__ __forceinline__ void ldsm_x4(uint32_t* r, uint32_t a) {
    asm volatile("ldmatrix.sync.aligned.m8n8.x4.shared.b16 {%0,%1,%2,%3}, [%4];"
                 : "=r"(r[0]), "=r"(r[1]), "=r"(r[2]), "=r"(r[3]) : "r"(a));
}
__device__ __forceinline__ void ldsm_x4_t(uint32_t* r, uint32_t a) {
    asm volatile("ldmatrix.sync.aligned.m8n8.x4.trans.shared.b16 {%0,%1,%2,%3}, [%4];"
                 : "=r"(r[0]), "=r"(r[1]), "=r"(r[2]), "=r"(r[3]) : "r"(a));
}
__device__ __forceinline__ void mma_bf16(float* c, const uint32_t* a, uint32_t b0, uint32_t b1) {
    asm volatile(
        "mma.sync.aligned.m16n8k16.row.col.f32.bf16.bf16.f32 "
        "{%0,%1,%2,%3}, {%4,%5,%6,%7}, {%8,%9}, {%0,%1,%2,%3};"
        : "+f"(c[0]), "+f"(c[1]), "+f"(c[2]), "+f"(c[3])
        : "r"(a[0]), "r"(a[1]), "r"(a[2]), "r"(a[3]), "r"(b0), "r"(b1));
}
__device__ __forceinline__ void mma_f16(float* c, const uint32_t* a, uint32_t b0, uint32_t b1) {
    asm volatile(
        "mma.sync.aligned.m16n8k16.row.col.f32.f16.f16.f32 "
        "{%0,%1,%2,%3}, {%4,%5,%6,%7}, {%8,%9}, {%0,%1,%2,%3};"
        : "+f"(c[0]), "+f"(c[1]), "+f"(c[2]), "+f"(c[3])
        : "r"(a[0]), "r"(a[1]), "r"(a[2]), "r"(a[3]), "r"(b0), "r"(b1));
}
__device__ __forceinline__ uint32_t packbf(float lo, float hi) {
    __nv_bfloat162 p = __floats2bfloat162_rn(lo, hi);
    return *(uint32_t*)&p;
}
__device__ __forceinline__ uint32_t packh2(float lo, float hi) {
    __half2 p = __floats2half2_rn(lo, hi);
    return *(uint32_t*)&p;
}
__device__ __forceinline__ uint32_t ex2_h2(uint32_t a) {
    uint32_t d;
    asm("ex2.approx.f16x2 %0, %1;" : "=r"(d) : "r"(a));
    return d;
}

// ---------------------------------------------------------------------------
// Stage 0: preconvert weights/biases to fused bf16 W' [320][256]
// ---------------------------------------------------------------------------
__global__ void preconv_kernel(
    const float* __restrict__ Wq, const float* __restrict__ bq,
    const float* __restrict__ Wk, const float* __restrict__ bk,
    const float* __restrict__ Wv, const float* __restrict__ bv)
{
    int idx = blockIdx.x * 256 + threadIdx.x;     // 0..20479
    int e0  = idx * 4;
    int o   = e0 >> 8, c = e0 & 255;
    float4 v;
    float scale = 1.f;
    if (o < 32)       { v = *(const float4*)&Wq[o*256 + c]; scale = QSC; }
    else if (o < 64)  { v = *(const float4*)&Wk[(o-32)*256 + c]; }
    else              { v = *(const float4*)&Wv[(o-64)*256 + c]; }
    uint2 u;
    u.x = packbf(v.x * scale, v.y * scale);
    u.y = packbf(v.z * scale, v.w * scale);
    *(uint2*)&g_wt[o*256 + c] = u;
    if (idx < 320)
        g_bias[idx] = (idx < 32) ? bq[idx]*QSC : (idx < 64 ? bk[idx-32] : bv[idx-64]);
}

// ---------------------------------------------------------------------------
// Stage 1: QKV projection with bf16 tensor cores. V output packed f16.
// smem bf16: xs[2][32][72] | ws[2][320][40]
// ---------------------------------------------------------------------------
#define XS_STR 72
#define WS_STR 40
#define QOFF_X0 0
#define QOFF_X1 2304
#define QOFF_W0 4608
#define QOFF_W1 17408
#define QKV_SMEM_BF 30208
#define QKV_SMEM_BYTES (QKV_SMEM_BF * 2)   // 60416

__global__ __launch_bounds__(256, 2) void qkv_kernel(const float* __restrict__ x)
{
    extern __shared__ __align__(16) __nv_bfloat16 smb[];
    const int t    = threadIdx.x;
    const int lane = t & 31;
    const int w    = t >> 5;
    const int g    = lane >> 2;
    const int tg   = lane & 3;
    const int wq   = w & 3;
    const int oh   = (w >> 2) * 160;
    const int b    = blockIdx.y;
    const int n0   = blockIdx.x * 64;

    const uint32_t xs_u[2] = { smem_u32(smb + QOFF_X0), smem_u32(smb + QOFF_X1) };
    const uint32_t ws_u[2] = { smem_u32(smb + QOFF_W0), smem_u32(smb + QOFF_W1) };

    const int xc   = t >> 3;
    const int xseg = (t & 7) * 8;
    auto ldx = [&](int ch0, float4* r) {
        const float* p = x + ((size_t)(b*CH + ch0 + xc) * NTOK) + n0 + xseg;
        r[0] = *(const float4*)p;
        r[1] = *(const float4*)(p + 4);
    };
    auto stx = [&](int s, const float4* r) {
        uint4 u;
        u.x = packbf(r[0].x, r[0].y); u.y = packbf(r[0].z, r[0].w);
        u.z = packbf(r[1].x, r[1].y); u.w = packbf(r[1].z, r[1].w);
        *(uint4*)(smb + (s ? QOFF_X1 : QOFF_X0) + xc*XS_STR + xseg) = u;
    };
    auto stw = [&](int s, int ch0) {
        #pragma unroll
        for (int i = 0; i < 5; i++) {
            int e = t + i*256;
            int row = e >> 2, seg = (e & 3) * 8;
            cp16(ws_u[s] + (uint32_t)(row*WS_STR + seg)*2,
                 g_wt + row*256 + ch0 + seg);
        }
        asm volatile("cp.async.commit_group;" ::: "memory");
    };

    float acc[20][4];
    #pragma unroll
    for (int nt = 0; nt < 20; nt++)
        #pragma unroll
        for (int k = 0; k < 4; k++) acc[nt][k] = 0.f;

    {
        float4 r[2];
        ldx(0, r); stw(0, 0); stx(0, r);
        asm volatile("cp.async.wait_group 0;" ::: "memory");
        __syncthreads();
    }

    for (int ks = 0; ks < 8; ks++) {
        const int s = ks & 1;
        float4 xr[2];
        if (ks < 7) {
            ldx((ks+1)*32, xr);
            stw(s ^ 1, (ks+1)*32);
        }
        uint32_t qa[2][4];
        #pragma unroll
        for (int kt = 0; kt < 2; kt++) {
            int chr = kt*16 + (lane & 7) + ((lane >> 4) & 1) * 8;
            int tok = wq*16 + ((lane >> 3) & 1) * 8;
            ldsm_x4_t(qa[kt], xs_u[s] + (uint32_t)(chr*XS_STR + tok)*2);
        }
        #pragma unroll
        for (int nt = 0; nt < 20; nt++) {
            uint32_t kb[4];
            int row = oh + nt*8 + (lane & 7);
            int col = (lane >> 3) * 8;
            ldsm_x4(kb, ws_u[s] + (uint32_t)(row*WS_STR + col)*2);
            mma_bf16(acc[nt], qa[0], kb[0], kb[1]);
            mma_bf16(acc[nt], qa[1], kb[2], kb[3]);
        }
        if (ks < 7) {
            stx(s ^ 1, xr);
            asm volatile("cp.async.wait_group 0;" ::: "memory");
        }
        __syncthreads();
    }

    int n_lo = n0 + wq*16 + g;
    #pragma unroll
    for (int nt = 0; nt < 20; nt++) {
        int o = oh + nt*8 + 2*tg;
        float b0 = g_bias[o], b1 = g_bias[o+1];
        float v0 = acc[nt][0] + b0, v1 = acc[nt][1] + b1;
        float v2 = acc[nt][2] + b0, v3 = acc[nt][3] + b1;
        if (o < 32) {        // q: bf16
            __nv_bfloat16* dst = g_q + (size_t)b * NTOK * INTER;
            *(uint32_t*)&dst[(size_t)(n_lo    ) * INTER + o] = packbf(v0, v1);
            *(uint32_t*)&dst[(size_t)(n_lo + 8) * INTER + o] = packbf(v2, v3);
        } else if (o < 64) { // k: bf16
            __nv_bfloat16* dst = g_k + (size_t)b * NTOK * INTER;
            *(uint32_t*)&dst[(size_t)(n_lo    ) * INTER + (o-32)] = packbf(v0, v1);
            *(uint32_t*)&dst[(size_t)(n_lo + 8) * INTER + (o-32)] = packbf(v2, v3);
        } else {             // v: f16
            __half* dst = g_v + (size_t)b * NTOK * CH;
            *(uint32_t*)&dst[(size_t)(n_lo    ) * CH + (o-64)] = packh2(v0, v1);
            *(uint32_t*)&dst[(size_t)(n_lo + 8) * CH + (o-64)] = packh2(v2, v3);
        }
    }
}

// ---------------------------------------------------------------------------
// Stage 2: TC flash attention. Q-tile 128, 512 threads, 16 warps.
// 3-stage cp.async pipeline, ONE __syncthreads + one 64-thr pair bar per iter.
// QK bf16; P/V f16; exp via ex2.approx.f16x2; l via ones-B MMA.
// Warp w: i-tile (w&7)*16, half = w>>3 (j-half for QK, channel-half for PV).
// smem bf16-units: Q[128][40] | K[3][64][40] | V[3][64][264] | P[128][72]
// ---------------------------------------------------------------------------
#define SQB 40
#define SVB 264
#define SPB 72
#define OFFQ 0
#define OFFK 5120
#define OFFV 12800
#define OFFP 63488
#define KBUF 2560
#define VBUF 16896
#define ATT_SMEM_BF 72704
#define ATT_SMEM_BYTES (ATT_SMEM_BF * 2)   // 145408

__global__ __launch_bounds__(512, 1) void attn_kernel(
    const float* __restrict__ x, const float* __restrict__ gamma_p,
    float* __restrict__ out)
{
    extern __shared__ __align__(16) __nv_bfloat16 smb[];

    const int t    = threadIdx.x;
    const int lane = t & 31;
    const int w    = t >> 5;        // 0..15
    const int g    = lane >> 2;
    const int tg   = lane & 3;
    const int iw   = w & 7;
    const int ib   = iw * 16;       // i-tile base (0..112)
    const int half = w >> 3;
    const int cb   = half * 128;
    const int jh   = half * 32;
    const int b    = blockIdx.y;
    const int i0   = blockIdx.x * 128;

    const uint32_t q_u  = smem_u32(smb + OFFQ);
    const uint32_t k_u0 = smem_u32(smb + OFFK);
    const uint32_t v_u0 = smem_u32(smb + OFFV);
    const uint32_t p_u  = smem_u32(smb + OFFP);
    const uint32_t bones = 0x3C003C00u;   // f16 {1,1}

    auto stage = [&](int s, int j0) {
        if (t < 256) {   // K tile [64][32] bf16
            int row = t >> 2, c = t & 3;
            cp16(k_u0 + (uint32_t)(s*KBUF + row*SQB + c*8)*2,
                 g_k + ((size_t)(b*NTOK + j0 + row) * INTER) + c*8);
        }
        {   // V tile [64][256] f16
            int row = t >> 3, cs = t & 7;
            const __half* vsrc = g_v + ((size_t)(b*NTOK + j0 + row) * CH);
            uint32_t vdst = v_u0 + (uint32_t)(s*VBUF + row*SVB)*2;
            #pragma unroll
            for (int k = 0; k < 4; k++) {
                int ch = (cs + 8*k) * 8;
                cp16(vdst + ch*2, vsrc + ch);
            }
        }
        asm volatile("cp.async.commit_group;" ::: "memory");
    };

    {   // prologue: G0 = Q [128][32]; G1 = stage0; G2 = stage1
        int row = t >> 2, c = t & 3;
        cp16(q_u + (uint32_t)(row*SQB + c*8)*2,
             g_q + ((size_t)(b*NTOK + i0 + row) * INTER) + c*8);
        asm volatile("cp.async.commit_group;" ::: "memory");
    }
    stage(0, 0);
    stage(1, 64);
    asm volatile("cp.async.wait_group 2;" ::: "memory");   // Q landed
    __syncthreads();                                       // Q visible

    uint32_t qa[2][4];
    #pragma unroll
    for (int kt = 0; kt < 2; kt++) {
        int row = ib + (lane & 7) + ((lane >> 3) & 1) * 8;
        int col = kt*16 + ((lane >> 4) & 1) * 8;
        ldsm_x4(qa[kt], q_u + (uint32_t)(row*SQB + col)*2);
    }

    float acc[16][4];
    #pragma unroll
    for (int nt = 0; nt < 16; nt++)
        #pragma unroll
        for (int k = 0; k < 4; k++) acc[nt][k] = 0.f;
    float lacc[4] = {0.f, 0.f, 0.f, 0.f};   // ones-MMA row sums

    for (int jt = 0; jt < 64; jt++) {
        const int s = jt % 3;

        if (jt < 63) asm volatile("cp.async.wait_group 1;" ::: "memory");
        else         asm volatile("cp.async.wait_group 0;" ::: "memory");
        __syncthreads();   // buf jt visible; everyone done with iter jt-1

        // restage: target buf (jt+2)%3 == (jt-1)%3, consumed at iter jt-1 -> safe
        if (jt + 2 < 64) stage((jt + 2) % 3, (jt + 2) * 64);

        const uint32_t k_u = k_u0 + (uint32_t)(s*KBUF)*2;
        const uint32_t v_u = v_u0 + (uint32_t)(s*VBUF)*2;

        // ---- QK^T on this warp's j-half: S[16][32] (log2 units) ----
        float sfr[4][4];
        #pragma unroll
        for (int j8 = 0; j8 < 4; j8++) {
            sfr[j8][0] = sfr[j8][1] = sfr[j8][2] = sfr[j8][3] = 0.f;
            uint32_t kb[4];
            int row = jh + j8*8 + (lane & 7);
            int col = (lane >> 3) * 8;
            ldsm_x4(kb, k_u + (uint32_t)(row*SQB + col)*2);
            mma_bf16(sfr[j8], qa[0], kb[0], kb[1]);
            mma_bf16(sfr[j8], qa[1], kb[2], kb[3]);
        }

        // ---- exp2 in f16x2, store P (f16) ----
        #pragma unroll
        for (int j8 = 0; j8 < 4; j8++) {
            uint32_t plo = ex2_h2(packh2(sfr[j8][0], sfr[j8][1]));
            uint32_t phi = ex2_h2(packh2(sfr[j8][2], sfr[j8][3]));
            int col = jh + j8*8 + 2*tg;
            *(uint32_t*)(smb + OFFP + (ib + g    )*SPB + col) = plo;
            *(uint32_t*)(smb + OFFP + (ib + 8 + g)*SPB + col) = phi;
        }

        // pair barrier: warps {iw, iw+8} both finished their P half
        asm volatile("bar.sync %0, 64;" :: "r"(1 + iw) : "memory");

        // ---- PV (f16): O[16][128] += P[16][64] x V[64][128]; l += P x ones ----
        #pragma unroll
        for (int kt = 0; kt < 4; kt++) {
            uint32_t pa[4];
            {
                int row = ib + (lane & 7) + ((lane >> 3) & 1) * 8;
                int col = kt*16 + ((lane >> 4) & 1) * 8;
                ldsm_x4(pa, p_u + (uint32_t)(row*SPB + col)*2);
            }
            mma_f16(lacc, pa, bones, bones);
            #pragma unroll
            for (int np = 0; np < 8; np++) {
                uint32_t vb[4];
                int row = kt*16 + ((lane >> 3) & 1)*8 + (lane & 7);
                int col = cb + (np*2 + (lane >> 4)) * 8;
                ldsm_x4_t(vb, v_u + (uint32_t)(row*SVB + col)*2);
                mma_f16(acc[2*np    ], pa, vb[0], vb[1]);
                mma_f16(acc[2*np + 1], pa, vb[2], vb[3]);
            }
        }
    }

    // ---- normalize (lacc cols all equal row sum; c0=row g, c2=row g+8) ----
    float li0 = 1.f / lacc[0];
    float li1 = 1.f / lacc[2];
    #pragma unroll
    for (int nt = 0; nt < 16; nt++) {
        acc[nt][0] *= li0; acc[nt][1] *= li0;
        acc[nt][2] *= li1; acc[nt][3] *= li1;
    }

    // ---- epilogue: two 64-query halves through smem transpose ----
    const float gmm = gamma_p[0];
    float (*ot)[68] = (float (*)[68])smb;   // [256][68] fp32
    for (int h = 0; h < 2; h++) {
        __syncthreads();
        if ((iw >> 2) == h) {
            int il = (ib & 63) + g;   // 0..63 within half
            #pragma unroll
            for (int nt = 0; nt < 16; nt++) {
                int c = cb + nt*8 + 2*tg;
                ot[c  ][il  ] = acc[nt][0];
                ot[c+1][il  ] = acc[nt][1];
                ot[c  ][il+8] = acc[nt][2];
                ot[c+1][il+8] = acc[nt][3];
            }
        }
        __syncthreads();
        {   // 512 threads: c = t>>1, token segment (t&1)*32 (8 float4)
            int c = t >> 1, seg = (t & 1) * 32;
            size_t base = ((size_t)(b*CH + c)) * NTOK + i0 + h*64 + seg;
            const float4* xp = (const float4*)(x + base);
            float4* op = (float4*)(out + base);
            #pragma unroll
            for (int i4 = 0; i4 < 8; i4++) {
                float4 xv = xp[i4];
                float4 r4;
                r4.x = gmm * ot[c][seg + i4*4 + 0] + xv.x;
                r4.y = gmm * ot[c][seg + i4*4 + 1] + xv.y;
                r4.z = gmm * ot[c][seg + i4*4 + 2] + xv.z;
                r4.w = gmm * ot[c][seg + i4*4 + 3] + xv.w;
                op[i4] = r4;
            }
        }
    }
}

// ---------------------------------------------------------------------------
extern "C" void kernel_launch(void* const* d_in, const int* in_sizes, int n_in,
                              void* d_out, int out_size)
{
    const float* x  = (const float*)d_in[0];
    const float* Wq = (const float*)d_in[1];
    const float* bq = (const float*)d_in[2];
    const float* Wk = (const float*)d_in[3];
    const float* bk = (const float*)d_in[4];
    const float* Wv = (const float*)d_in[5];
    const float* bv = (const float*)d_in[6];
    const float* gm = (const float*)d_in[7];
    float* out = (float*)d_out;

    cudaFuncSetAttribute(qkv_kernel,  cudaFuncAttributeMaxDynamicSharedMemorySize, QKV_SMEM_BYTES);
    cudaFuncSetAttribute(attn_kernel, cudaFuncAttributeMaxDynamicSharedMemorySize, ATT_SMEM_BYTES);

    preconv_kernel<<<80, 256>>>(Wq, bq, Wk, bk, Wv, bv);

    dim3 g1(NTOK / 64, BATCH);
    qkv_kernel<<<g1, 256, QKV_SMEM_BYTES>>>(x);

    dim3 g2(NTOK / 128, BATCH);
    attn_kernel<<<g2, 512, ATT_SMEM_BYTES>>>(x, gm, out);
}

// round 10
// speedup vs baseline: 1.0235x; 1.0235x over previous
#include <cuda_runtime.h>
#include <cuda_bf16.h>
#include <cuda_fp16.h>
#include <math.h>
#include <stdint.h>

#define BATCH 4
#define CH    256
#define NTOK  4096
#define INTER 32
// QK scale with log2(e) folded in: scores come out in log2 units -> exp2
#define QSC (0.17677669529663687f * 1.4426950408889634f)

// Scratch (no allocation allowed)
__device__ __nv_bfloat16 g_q[(size_t)BATCH * NTOK * INTER];
__device__ __nv_bfloat16 g_k[(size_t)BATCH * NTOK * INTER];
__device__ __half        g_v[(size_t)BATCH * NTOK * CH];
__device__ __nv_bfloat16 g_wt[320 * 256];   // fused [Wq;Wk;Wv], q rows pre-scaled
__device__ float         g_bias[320];

// ---------------------------------------------------------------------------
// ptx helpers (sm_90-era only: mma.sync / ldmatrix / cp.async — compile-safe)
// ---------------------------------------------------------------------------
__device__ __forceinline__ uint32_t smem_u32(const void* p) {
    return (uint32_t)__cvta_generic_to_shared(p);
}
__device__ __forceinline__ void cp16(uint32_t dst, const void* src) {
    asm volatile("cp.async.cg.shared.global [%0], [%1], 16;" :: "r"(dst), "l"(src));
}
__device__ __forceinline__ void ldsm_x4(uint32_t* r, uint32_t a) {
    asm volatile("ldmatrix.sync.aligned.m8n8.x4.shared.b16 {%0,%1,%2,%3}, [%4];"
                 : "=r"(r[0]), "=r"(r[1]), "=r"(r[2]), "=r"(r[3]) : "r"(a));
}
__device__ __forceinline__ void ldsm_x4_t(uint32_t* r, uint32_t a) {
    asm volatile("ldmatrix.sync.aligned.m8n8.x4.trans.shared.b16 {%0,%1,%2,%3}, [%4];"
                 : "=r"(r[0]), "=r"(r[1]), "=r"(r[2]), "=r"(r[3]) : "r"(a));
}
__device__ __forceinline__ void mma_bf16(float* c, const uint32_t* a, uint32_t b0, uint32_t b1) {
    asm volatile(
        "mma.sync.aligned.m16n8k16.row.col.f32.bf16.bf16.f32 "
        "{%0,%1,%2,%3}, {%4,%5,%6,%7}, {%8,%9}, {%0,%1,%2,%3};"
        : "+f"(c[0]), "+f"(c[1]), "+f"(c[2]), "+f"(c[3])
        : "r"(a[0]), "r"(a[1]), "r"(a[2]), "r"(a[3]), "r"(b0), "r"(b1));
}
__device__ __forceinline__ void mma_f16(float* c, const uint32_t* a, uint32_t b0, uint32_t b1) {
    asm volatile(
        "mma.sync.aligned.m16n8k16.row.col.f32.f16.f16.f32 "
        "{%0,%1,%2,%3}, {%4,%5,%6,%7}, {%8,%9}, {%0,%1,%2,%3};"
        : "+f"(c[0]), "+f"(c[1]), "+f"(c[2]), "+f"(c[3])
        : "r"(a[0]), "r"(a[1]), "r"(a[2]), "r"(a[3]), "r"(b0), "r"(b1));
}
__device__ __forceinline__ uint32_t packbf(float lo, float hi) {
    __nv_bfloat162 p = __floats2bfloat162_rn(lo, hi);
    return *(uint32_t*)&p;
}
__device__ __forceinline__ uint32_t packh2(float lo, float hi) {
    __half2 p = __floats2half2_rn(lo, hi);
    return *(uint32_t*)&p;
}
__device__ __forceinline__ uint32_t ex2_h2(uint32_t a) {
    uint32_t d;
    asm("ex2.approx.f16x2 %0, %1;" : "=r"(d) : "r"(a));
    return d;
}

// ---------------------------------------------------------------------------
// Stage 0: preconvert weights/biases to fused bf16 W' [320][256]
// ---------------------------------------------------------------------------
__global__ void preconv_kernel(
    const float* __restrict__ Wq, const float* __restrict__ bq,
    const float* __restrict__ Wk, const float* __restrict__ bk,
    const float* __restrict__ Wv, const float* __restrict__ bv)
{
    int idx = blockIdx.x * 256 + threadIdx.x;     // 0..20479
    int e0  = idx * 4;
    int o   = e0 >> 8, c = e0 & 255;
    float4 v;
    float scale = 1.f;
    if (o < 32)       { v = *(const float4*)&Wq[o*256 + c]; scale = QSC; }
    else if (o < 64)  { v = *(const float4*)&Wk[(o-32)*256 + c]; }
    else              { v = *(const float4*)&Wv[(o-64)*256 + c]; }
    uint2 u;
    u.x = packbf(v.x * scale, v.y * scale);
    u.y = packbf(v.z * scale, v.w * scale);
    *(uint2*)&g_wt[o*256 + c] = u;
    if (idx < 320)
        g_bias[idx] = (idx < 32) ? bq[idx]*QSC : (idx < 64 ? bk[idx-32] : bv[idx-64]);
}

// ---------------------------------------------------------------------------
// Stage 1: QKV projection, bf16 tensor cores (proven r8 version; V out f16)
// smem bf16: xs[2][32][72] | ws[2][320][40]
// ---------------------------------------------------------------------------
#define XS_STR 72
#define WS_STR 40
#define QOFF_X0 0
#define QOFF_X1 2304
#define QOFF_W0 4608
#define QOFF_W1 17408
#define QKV_SMEM_BF 30208
#define QKV_SMEM_BYTES (QKV_SMEM_BF * 2)

__global__ __launch_bounds__(256, 2) void qkv_kernel(const float* __restrict__ x)
{
    extern __shared__ __align__(16) __nv_bfloat16 smb[];
    const int t    = threadIdx.x;
    const int lane = t & 31;
    const int w    = t >> 5;
    const int g    = lane >> 2;
    const int tg   = lane & 3;
    const int wq   = w & 3;
    const int oh   = (w >> 2) * 160;
    const int b    = blockIdx.y;
    const int n0   = blockIdx.x * 64;

    const uint32_t xs_u[2] = { smem_u32(smb + QOFF_X0), smem_u32(smb + QOFF_X1) };
    const uint32_t ws_u[2] = { smem_u32(smb + QOFF_W0), smem_u32(smb + QOFF_W1) };

    const int xc   = t >> 3;
    const int xseg = (t & 7) * 8;
    auto ldx = [&](int ch0, float4* r) {
        const float* p = x + ((size_t)(b*CH + ch0 + xc) * NTOK) + n0 + xseg;
        r[0] = *(const float4*)p;
        r[1] = *(const float4*)(p + 4);
    };
    auto stx = [&](int s, const float4* r) {
        uint4 u;
        u.x = packbf(r[0].x, r[0].y); u.y = packbf(r[0].z, r[0].w);
        u.z = packbf(r[1].x, r[1].y); u.w = packbf(r[1].z, r[1].w);
        *(uint4*)(smb + (s ? QOFF_X1 : QOFF_X0) + xc*XS_STR + xseg) = u;
    };
    auto stw = [&](int s, int ch0) {
        #pragma unroll
        for (int i = 0; i < 5; i++) {
            int e = t + i*256;
            int row = e >> 2, seg = (e & 3) * 8;
            cp16(ws_u[s] + (uint32_t)(row*WS_STR + seg)*2, g_wt + row*256 + ch0 + seg);
        }
        asm volatile("cp.async.commit_group;" ::: "memory");
    };

    float acc[20][4];
    #pragma unroll
    for (int nt = 0; nt < 20; nt++)
        #pragma unroll
        for (int k = 0; k < 4; k++) acc[nt][k] = 0.f;

    {
        float4 r[2];
        ldx(0, r); stw(0, 0); stx(0, r);
        asm volatile("cp.async.wait_group 0;" ::: "memory");
        __syncthreads();
    }

    for (int ks = 0; ks < 8; ks++) {
        const int s = ks & 1;
        float4 xr[2];
        if (ks < 7) { ldx((ks+1)*32, xr); stw(s ^ 1, (ks+1)*32); }
        uint32_t qa[2][4];
        #pragma unroll
        for (int kt = 0; kt < 2; kt++) {
            int chr = kt*16 + (lane & 7) + ((lane >> 4) & 1) * 8;
            int tok = wq*16 + ((lane >> 3) & 1) * 8;
            ldsm_x4_t(qa[kt], xs_u[s] + (uint32_t)(chr*XS_STR + tok)*2);
        }
        #pragma unroll
        for (int nt = 0; nt < 20; nt++) {
            uint32_t kb[4];
            int row = oh + nt*8 + (lane & 7);
            int col = (lane >> 3) * 8;
            ldsm_x4(kb, ws_u[s] + (uint32_t)(row*WS_STR + col)*2);
            mma_bf16(acc[nt], qa[0], kb[0], kb[1]);
            mma_bf16(acc[nt], qa[1], kb[2], kb[3]);
        }
        if (ks < 7) {
            stx(s ^ 1, xr);
            asm volatile("cp.async.wait_group 0;" ::: "memory");
        }
        __syncthreads();
    }

    int n_lo = n0 + wq*16 + g;
    #pragma unroll
    for (int nt = 0; nt < 20; nt++) {
        int o = oh + nt*8 + 2*tg;
        float b0 = g_bias[o], b1 = g_bias[o+1];
        float v0 = acc[nt][0] + b0, v1 = acc[nt][1] + b1;
        float v2 = acc[nt][2] + b0, v3 = acc[nt][3] + b1;
        if (o < 32) {
            __nv_bfloat16* dst = g_q + (size_t)b * NTOK * INTER;
            *(uint32_t*)&dst[(size_t)(n_lo    ) * INTER + o] = packbf(v0, v1);
            *(uint32_t*)&dst[(size_t)(n_lo + 8) * INTER + o] = packbf(v2, v3);
        } else if (o < 64) {
            __nv_bfloat16* dst = g_k + (size_t)b * NTOK * INTER;
            *(uint32_t*)&dst[(size_t)(n_lo    ) * INTER + (o-32)] = packbf(v0, v1);
            *(uint32_t*)&dst[(size_t)(n_lo + 8) * INTER + (o-32)] = packbf(v2, v3);
        } else {
            __half* dst = g_v + (size_t)b * NTOK * CH;
            *(uint32_t*)&dst[(size_t)(n_lo    ) * CH + (o-64)] = packh2(v0, v1);
            *(uint32_t*)&dst[(size_t)(n_lo + 8) * CH + (o-64)] = packh2(v2, v3);
        }
    }
}

// ---------------------------------------------------------------------------
// Stage 2: mma.sync flash attention. Q-tile 128, j-tile 128, 512 thr, 16 warps.
// 32 iterations (barrier overhead halved vs r7). r7's proven sync ordering:
//   syncA (prev done) -> restage s^1 -> wait_group -> syncV -> QK/exp/P
//   -> pair bar -> PV.
// QK bf16; P/V f16; exp via ex2.approx.f16x2; QK+exp fused per j8 (low regs).
// Warp w: i-tile (w&7)*16, half = w>>3 (j-half 64 for QK, channel-half for PV).
// smem (2B elem offsets): Q[128][40] | K[2][128][40] | V[2][128][264]
//                         | P[128][136] | lsum f32[256]
// ---------------------------------------------------------------------------
#define SQB 40
#define SVB 264
#define SPB 136
#define OFFQ 0
#define OFFK 5120
#define OFFV 15360
#define OFFP 82944
#define KBUF 5120
#define VBUF 33792
#define ATT_SMEM_EL 100352
#define ATT_SMEM_BYTES (ATT_SMEM_EL*2 + 1024)   // 201728 + lsum

__global__ __launch_bounds__(512, 1) void attn_kernel(
    const float* __restrict__ x, const float* __restrict__ gamma_p,
    float* __restrict__ out)
{
    extern __shared__ __align__(16) __nv_bfloat16 smb[];
    float* lsum = (float*)(smb + ATT_SMEM_EL);

    const int t    = threadIdx.x;
    const int lane = t & 31;
    const int w    = t >> 5;        // 0..15
    const int g    = lane >> 2;
    const int tg   = lane & 3;
    const int iw   = w & 7;
    const int ib   = iw * 16;       // i-tile base (0..112)
    const int half = w >> 3;
    const int cb   = half * 128;    // channel half for PV
    const int jh   = half * 64;     // j-half (64 wide) for QK/exp
    const int b    = blockIdx.y;
    const int i0   = blockIdx.x * 128;

    const uint32_t q_u  = smem_u32(smb + OFFQ);
    const uint32_t k_u0 = smem_u32(smb + OFFK);
    const uint32_t v_u0 = smem_u32(smb + OFFV);
    const uint32_t p_u  = smem_u32(smb + OFFP);

    auto stage = [&](int s, int j0) {
        {   // K tile [128][32] bf16: 512 cp16
            int row = t >> 2, c = t & 3;
            cp16(k_u0 + (uint32_t)(s*KBUF + row*SQB + c*8)*2,
                 g_k + ((size_t)(b*NTOK + j0 + row) * INTER) + c*8);
        }
        #pragma unroll
        for (int i = 0; i < 8; i++) {   // V tile [128][256] f16: 4096 cp16
            int e = t + i*512;
            int row = e >> 5, ch = e & 31;
            cp16(v_u0 + (uint32_t)(s*VBUF + row*SVB + ch*8)*2,
                 g_v + ((size_t)(b*NTOK + j0 + row) * CH) + ch*8);
        }
        asm volatile("cp.async.commit_group;" ::: "memory");
    };

    {   // prologue: Q [128][32] (group), then tile 0
        int row = t >> 2, c = t & 3;
        cp16(q_u + (uint32_t)(row*SQB + c*8)*2,
             g_q + ((size_t)(b*NTOK + i0 + row) * INTER) + c*8);
        asm volatile("cp.async.commit_group;" ::: "memory");
    }
    stage(0, 0);
    asm volatile("cp.async.wait_group 1;" ::: "memory");   // Q landed
    __syncthreads();                                       // Q visible

    uint32_t qa[2][4];
    #pragma unroll
    for (int kt = 0; kt < 2; kt++) {
        int row = ib + (lane & 7) + ((lane >> 3) & 1) * 8;
        int col = kt*16 + ((lane >> 4) & 1) * 8;
        ldsm_x4(qa[kt], q_u + (uint32_t)(row*SQB + col)*2);
    }

    float acc[16][4];
    #pragma unroll
    for (int nt = 0; nt < 16; nt++)
        #pragma unroll
        for (int k = 0; k < 4; k++) acc[nt][k] = 0.f;
    float l0 = 0.f, l1 = 0.f;

    for (int jt = 0; jt < 32; jt++) {
        const int s = jt & 1;

        __syncthreads();   // [A] prev iter fully done: buf s^1 and P free
        if (jt < 31) {
            stage(s ^ 1, (jt + 1) * 128);
            asm volatile("cp.async.wait_group 1;" ::: "memory");  // buf s landed
        } else {
            asm volatile("cp.async.wait_group 0;" ::: "memory");
        }
        __syncthreads();   // [V] buf s visible to ALL threads

        const uint32_t k_u = k_u0 + (uint32_t)(s*KBUF)*2;
        const uint32_t v_u = v_u0 + (uint32_t)(s*VBUF)*2;

        // ---- QK^T + exp + P-store fused per j8 (8 blocks cover j-half 64) ----
        #pragma unroll
        for (int j8 = 0; j8 < 8; j8++) {
            float sfr[4];
            sfr[0] = sfr[1] = sfr[2] = sfr[3] = 0.f;
            uint32_t kb[4];
            int row = jh + j8*8 + (lane & 7);
            int col = (lane >> 3) * 8;
            ldsm_x4(kb, k_u + (uint32_t)(row*SQB + col)*2);
            mma_bf16(sfr, qa[0], kb[0], kb[1]);
            mma_bf16(sfr, qa[1], kb[2], kb[3]);

            uint32_t plo = ex2_h2(packh2(sfr[0], sfr[1]));
            uint32_t phi = ex2_h2(packh2(sfr[2], sfr[3]));
            float2 flo = __half22float2(*(__half2*)&plo);
            float2 fhi = __half22float2(*(__half2*)&phi);
            l0 += flo.x + flo.y;
            l1 += fhi.x + fhi.y;
            int pcol = jh + j8*8 + 2*tg;
            *(uint32_t*)(smb + OFFP + (ib + g    )*SPB + pcol) = plo;
            *(uint32_t*)(smb + OFFP + (ib + 8 + g)*SPB + pcol) = phi;
        }

        // [B] pair barrier: warps {iw, iw+8} both finished their P half
        asm volatile("bar.sync %0, 64;" :: "r"(1 + iw) : "memory");

        // ---- PV (f16): O[16][128] += P[16][128] x V[128][128] ----
        #pragma unroll
        for (int kt = 0; kt < 8; kt++) {
            uint32_t pa[4];
            {
                int row = ib + (lane & 7) + ((lane >> 3) & 1) * 8;
                int col = kt*16 + ((lane >> 4) & 1) * 8;
                ldsm_x4(pa, p_u + (uint32_t)(row*SPB + col)*2);
            }
            #pragma unroll
            for (int np = 0; np < 8; np++) {
                uint32_t vb[4];
                int row = kt*16 + ((lane >> 3) & 1)*8 + (lane & 7);
                int col = cb + (np*2 + (lane >> 4)) * 8;
                ldsm_x4_t(vb, v_u + (uint32_t)(row*SVB + col)*2);
                mma_f16(acc[2*np    ], pa, vb[0], vb[1]);
                mma_f16(acc[2*np + 1], pa, vb[2], vb[3]);
            }
        }
    }

    // ---- combine l across quad lanes + across j-half warps ----
    l0 += __shfl_xor_sync(0xffffffffu, l0, 1);
    l0 += __shfl_xor_sync(0xffffffffu, l0, 2);
    l1 += __shfl_xor_sync(0xffffffffu, l1, 1);
    l1 += __shfl_xor_sync(0xffffffffu, l1, 2);
    if (tg == 0) {
        lsum[(ib + g    )*2 + half] = l0;
        lsum[(ib + 8 + g)*2 + half] = l1;
    }
    __syncthreads();
    float li0 = 1.f / (lsum[(ib + g    )*2] + lsum[(ib + g    )*2 + 1]);
    float li1 = 1.f / (lsum[(ib + 8 + g)*2] + lsum[(ib + 8 + g)*2 + 1]);
    #pragma unroll
    for (int nt = 0; nt < 16; nt++) {
        acc[nt][0] *= li0; acc[nt][1] *= li0;
        acc[nt][2] *= li1; acc[nt][3] *= li1;
    }

    // ---- epilogue: two 64-query halves through smem transpose ----
    const float gmm = gamma_p[0];
    float (*ot)[68] = (float (*)[68])smb;   // [256][68] fp32; lsum beyond
    for (int h = 0; h < 2; h++) {
        __syncthreads();
        if ((iw >> 2) == h) {
            int il = (ib & 63) + g;   // 0..63 within half
            #pragma unroll
            for (int nt = 0; nt < 16; nt++) {
                int c = cb + nt*8 + 2*tg;
                ot[c  ][il  ] = acc[nt][0];
                ot[c+1][il  ] = acc[nt][1];
                ot[c  ][il+8] = acc[nt][2];
                ot[c+1][il+8] = acc[nt][3];
            }
        }
        __syncthreads();
        {   // 512 threads: c = t>>1, token segment (t&1)*32 (8 float4)
            int c = t >> 1, seg = (t & 1) * 32;
            size_t base = ((size_t)(b*CH + c)) * NTOK + i0 + h*64 + seg;
            const float4* xp = (const float4*)(x + base);
            float4* op = (float4*)(out + base);
            #pragma unroll
            for (int i4 = 0; i4 < 8; i4++) {
                float4 xv = xp[i4];
                float4 r4;
                r4.x = gmm * ot[c][seg + i4*4 + 0] + xv.x;
                r4.y = gmm * ot[c][seg + i4*4 + 1] + xv.y;
                r4.z = gmm * ot[c][seg + i4*4 + 2] + xv.z;
                r4.w = gmm * ot[c][seg + i4*4 + 3] + xv.w;
                op[i4] = r4;
            }
        }
    }
}

// ---------------------------------------------------------------------------
extern "C" void kernel_launch(void* const* d_in, const int* in_sizes, int n_in,
                              void* d_out, int out_size)
{
    const float* x  = (const float*)d_in[0];
    const float* Wq = (const float*)d_in[1];
    const float* bq = (const float*)d_in[2];
    const float* Wk = (const float*)d_in[3];
    const float* bk = (const float*)d_in[4];
    const float* Wv = (const float*)d_in[5];
    const float* bv = (const float*)d_in[6];
    const float* gm = (const float*)d_in[7];
    float* out = (float*)d_out;

    cudaFuncSetAttribute(qkv_kernel,  cudaFuncAttributeMaxDynamicSharedMemorySize, QKV_SMEM_BYTES);
    cudaFuncSetAttribute(attn_kernel, cudaFuncAttributeMaxDynamicSharedMemorySize, ATT_SMEM_BYTES);

    preconv_kernel<<<80, 256>>>(Wq, bq, Wk, bk, Wv, bv);

    dim3 g1(NTOK / 64, BATCH);
    qkv_kernel<<<g1, 256, QKV_SMEM_BYTES>>>(x);

    dim3 g2(NTOK / 128, BATCH);
    attn_kernel<<<g2, 512, ATT_SMEM_BYTES>>>(x, gm, out);
}

// round 11
// speedup vs baseline: 1.0332x; 1.0095x over previous
#include <cuda_runtime.h>
#include <cuda_bf16.h>
#include <math.h>
#include <stdint.h>

#define BATCH 4
#define CH    256
#define NTOK  4096
#define INTER 32
// QK scale with log2(e) folded in: scores come out in log2 units -> exp2
#define QSC (0.17677669529663687f * 1.4426950408889634f)

// Scratch (no allocation allowed)
__device__ __nv_bfloat16 g_q[(size_t)BATCH * NTOK * INTER];
__device__ __nv_bfloat16 g_k[(size_t)BATCH * NTOK * INTER];
__device__ __nv_bfloat16 g_v[(size_t)BATCH * NTOK * CH];
__device__ __nv_bfloat16 g_xb[(size_t)BATCH * CH * NTOK];   // x in bf16
__device__ __nv_bfloat16 g_wt[320 * 256];   // fused [Wq;Wk;Wv], q rows pre-scaled
__device__ float         g_bias[320];

// ---------------------------------------------------------------------------
// ptx helpers
// ---------------------------------------------------------------------------
__device__ __forceinline__ uint32_t smem_u32(const void* p) {
    return (uint32_t)__cvta_generic_to_shared(p);
}
__device__ __forceinline__ void cp16(uint32_t dst, const void* src) {
    asm volatile("cp.async.cg.shared.global [%0], [%1], 16;" :: "r"(dst), "l"(src));
}
__device__ __forceinline__ void ldsm_x4(uint32_t* r, uint32_t a) {
    asm volatile("ldmatrix.sync.aligned.m8n8.x4.shared.b16 {%0,%1,%2,%3}, [%4];"
                 : "=r"(r[0]), "=r"(r[1]), "=r"(r[2]), "=r"(r[3]) : "r"(a));
}
__device__ __forceinline__ void ldsm_x4_t(uint32_t* r, uint32_t a) {
    asm volatile("ldmatrix.sync.aligned.m8n8.x4.trans.shared.b16 {%0,%1,%2,%3}, [%4];"
                 : "=r"(r[0]), "=r"(r[1]), "=r"(r[2]), "=r"(r[3]) : "r"(a));
}
__device__ __forceinline__ void mma_bf16(float* c, const uint32_t* a, uint32_t b0, uint32_t b1) {
    asm volatile(
        "mma.sync.aligned.m16n8k16.row.col.f32.bf16.bf16.f32 "
        "{%0,%1,%2,%3}, {%4,%5,%6,%7}, {%8,%9}, {%0,%1,%2,%3};"
        : "+f"(c[0]), "+f"(c[1]), "+f"(c[2]), "+f"(c[3])
        : "r"(a[0]), "r"(a[1]), "r"(a[2]), "r"(a[3]), "r"(b0), "r"(b1));
}
__device__ __forceinline__ uint32_t packbf(float lo, float hi) {
    __nv_bfloat162 p = __floats2bfloat162_rn(lo, hi);
    return *(uint32_t*)&p;
}
__device__ __forceinline__ float ex2(float x) {
    float y; asm("ex2.approx.f32 %0, %1;" : "=f"(y) : "f"(x)); return y;
}

// ---------------------------------------------------------------------------
// Stage 0: preconvert weights/bias (blocks 0..79) AND x -> bf16 (blocks 80+)
// ---------------------------------------------------------------------------
__global__ void preconv_kernel(
    const float* __restrict__ x,
    const float* __restrict__ Wq, const float* __restrict__ bq,
    const float* __restrict__ Wk, const float* __restrict__ bk,
    const float* __restrict__ Wv, const float* __restrict__ bv)
{
    if (blockIdx.x < 80) {
        int idx = blockIdx.x * 256 + threadIdx.x;     // 0..20479
        int e0  = idx * 4;
        int o   = e0 >> 8, c = e0 & 255;
        float4 v;
        float scale = 1.f;
        if (o < 32)       { v = *(const float4*)&Wq[o*256 + c]; scale = QSC; }
        else if (o < 64)  { v = *(const float4*)&Wk[(o-32)*256 + c]; }
        else              { v = *(const float4*)&Wv[(o-64)*256 + c]; }
        uint2 u;
        u.x = packbf(v.x * scale, v.y * scale);
        u.y = packbf(v.z * scale, v.w * scale);
        *(uint2*)&g_wt[o*256 + c] = u;
        if (idx < 320)
            g_bias[idx] = (idx < 32) ? bq[idx]*QSC : (idx < 64 ? bk[idx-32] : bv[idx-64]);
    } else {
        // x convert: 2048 blocks x 256 thr x 8 elems = 4,194,304 elems
        size_t e0 = ((size_t)(blockIdx.x - 80) * 256 + threadIdx.x) * 8;
        float4 a = *(const float4*)(x + e0);
        float4 c = *(const float4*)(x + e0 + 4);
        uint4 u;
        u.x = packbf(a.x, a.y); u.y = packbf(a.z, a.w);
        u.z = packbf(c.x, c.y); u.w = packbf(c.z, c.w);
        *(uint4*)&g_xb[e0] = u;
    }
}

// ---------------------------------------------------------------------------
// Stage 1: QKV projection, bf16 tensor cores. Both x and W tiles staged via
// cp.async (x pre-converted to bf16) — no fp32 register round-trip.
// CTA = 64 tokens x 320 outputs; 8 warps: tok-tile (w&3)*16, out-half (w>>2)*160.
// smem bf16: xs[2][32][72] | ws[2][320][40]
// ---------------------------------------------------------------------------
#define XS_STR 72
#define WS_STR 40
#define QOFF_X0 0
#define QOFF_X1 2304
#define QOFF_W0 4608
#define QOFF_W1 17408
#define QKV_SMEM_BF 30208
#define QKV_SMEM_BYTES (QKV_SMEM_BF * 2)   // 60416

__global__ __launch_bounds__(256, 2) void qkv_kernel()
{
    extern __shared__ __align__(16) __nv_bfloat16 smb[];
    const int t    = threadIdx.x;
    const int lane = t & 31;
    const int w    = t >> 5;
    const int g    = lane >> 2;
    const int tg   = lane & 3;
    const int wq   = w & 3;
    const int oh   = (w >> 2) * 160;
    const int b    = blockIdx.y;
    const int n0   = blockIdx.x * 64;

    const uint32_t xs_u[2] = { smem_u32(smb + QOFF_X0), smem_u32(smb + QOFF_X1) };
    const uint32_t ws_u[2] = { smem_u32(smb + QOFF_W0), smem_u32(smb + QOFF_W1) };

    auto stage = [&](int s, int ch0) {
        {   // x tile [32 ch][64 tok] bf16: 256 cp16
            int row = t >> 3, ck = t & 7;
            cp16(xs_u[s] + (uint32_t)(row*XS_STR + ck*8)*2,
                 g_xb + ((size_t)(b*CH + ch0 + row) * NTOK) + n0 + ck*8);
        }
        #pragma unroll
        for (int i = 0; i < 5; i++) {   // W tile [320][32]: 1280 cp16
            int e = t + i*256;
            int row = e >> 2, seg = (e & 3) * 8;
            cp16(ws_u[s] + (uint32_t)(row*WS_STR + seg)*2,
                 g_wt + row*256 + ch0 + seg);
        }
        asm volatile("cp.async.commit_group;" ::: "memory");
    };

    float acc[20][4];
    #pragma unroll
    for (int nt = 0; nt < 20; nt++)
        #pragma unroll
        for (int k = 0; k < 4; k++) acc[nt][k] = 0.f;

    stage(0, 0);
    asm volatile("cp.async.wait_group 0;" ::: "memory");
    __syncthreads();

    for (int ks = 0; ks < 8; ks++) {
        const int s = ks & 1;
        if (ks < 7) stage(s ^ 1, (ks+1)*32);   // overlaps with compute below

        uint32_t qa[2][4];
        #pragma unroll
        for (int kt = 0; kt < 2; kt++) {
            int chr = kt*16 + (lane & 7) + ((lane >> 4) & 1) * 8;
            int tok = wq*16 + ((lane >> 3) & 1) * 8;
            ldsm_x4_t(qa[kt], xs_u[s] + (uint32_t)(chr*XS_STR + tok)*2);
        }
        #pragma unroll
        for (int nt = 0; nt < 20; nt++) {
            uint32_t kb[4];
            int row = oh + nt*8 + (lane & 7);
            int col = (lane >> 3) * 8;
            ldsm_x4(kb, ws_u[s] + (uint32_t)(row*WS_STR + col)*2);
            mma_bf16(acc[nt], qa[0], kb[0], kb[1]);
            mma_bf16(acc[nt], qa[1], kb[2], kb[3]);
        }
        if (ks < 7)
            asm volatile("cp.async.wait_group 0;" ::: "memory");
        __syncthreads();
    }

    int n_lo = n0 + wq*16 + g;
    #pragma unroll
    for (int nt = 0; nt < 20; nt++) {
        int o = oh + nt*8 + 2*tg;
        float b0 = g_bias[o], b1 = g_bias[o+1];
        uint32_t lo = packbf(acc[nt][0] + b0, acc[nt][1] + b1);
        uint32_t hi = packbf(acc[nt][2] + b0, acc[nt][3] + b1);
        __nv_bfloat16* dst; int ldo, oc;
        if (o < 32)      { dst = g_q; ldo = INTER; oc = o; }
        else if (o < 64) { dst = g_k; ldo = INTER; oc = o - 32; }
        else             { dst = g_v; ldo = CH;    oc = o - 64; }
        dst += (size_t)b * NTOK * ldo;
        *(uint32_t*)&dst[(size_t)(n_lo    ) * ldo + oc] = lo;
        *(uint32_t*)&dst[(size_t)(n_lo + 8) * ldo + oc] = hi;
    }
}

// ---------------------------------------------------------------------------
// Stage 2: bf16 TC flash attention (exact r7 / 178.8us version).
// Q-tile 128, 512 threads, 16 warps; j-tile 64, double-buffered.
// Per iter: sync (prev done) -> restage s^1 -> wait -> sync (s visible)
//           -> QK/exp/P -> pair bar -> PV.
// smem bf16: Q[128][40] | K[2][64][40] | V[2][64][264] | P[128][72] | lsum f32
// ---------------------------------------------------------------------------
#define SQB 40
#define SVB 264
#define SPB 72
#define OFFQ 0
#define OFFK 5120
#define OFFV 10240
#define OFFP 44032
#define KBUF 2560
#define VBUF 16896
#define ATT_SMEM_BF 53248
#define ATT_SMEM_BYTES (ATT_SMEM_BF*2 + 1024)   // 107520

__global__ __launch_bounds__(512, 1) void attn_kernel(
    const float* __restrict__ x, const float* __restrict__ gamma_p,
    float* __restrict__ out)
{
    extern __shared__ __align__(16) __nv_bfloat16 smb[];
    float* lsum = (float*)(smb + ATT_SMEM_BF);

    const int t    = threadIdx.x;
    const int lane = t & 31;
    const int w    = t >> 5;        // 0..15
    const int g    = lane >> 2;
    const int tg   = lane & 3;
    const int iw   = w & 7;
    const int ib   = iw * 16;       // i-tile base (0..112)
    const int half = w >> 3;
    const int cb   = half * 128;
    const int jh   = half * 32;
    const int b    = blockIdx.y;
    const int i0   = blockIdx.x * 128;

    const uint32_t q_u  = smem_u32(smb + OFFQ);
    const uint32_t k_u0 = smem_u32(smb + OFFK);
    const uint32_t v_u0 = smem_u32(smb + OFFV);
    const uint32_t p_u  = smem_u32(smb + OFFP);

    auto stage = [&](int s, int j0) {
        if (t < 256) {   // K tile [64][32]
            int row = t >> 2, c = t & 3;
            cp16(k_u0 + (uint32_t)(s*KBUF + row*SQB + c*8)*2,
                 g_k + ((size_t)(b*NTOK + j0 + row) * INTER) + c*8);
        }
        {   // V tile [64][256]: row = t>>3, 4 cp16 each
            int row = t >> 3, cs = t & 7;
            const __nv_bfloat16* vsrc = g_v + ((size_t)(b*NTOK + j0 + row) * CH);
            uint32_t vdst = v_u0 + (uint32_t)(s*VBUF + row*SVB)*2;
            #pragma unroll
            for (int k = 0; k < 4; k++) {
                int ch = (cs + 8*k) * 8;
                cp16(vdst + ch*2, vsrc + ch);
            }
        }
        asm volatile("cp.async.commit_group;" ::: "memory");
    };

    {   // prologue: Q [128][32] (one group), then tile 0
        int row = t >> 2, c = t & 3;
        cp16(q_u + (uint32_t)(row*SQB + c*8)*2,
             g_q + ((size_t)(b*NTOK + i0 + row) * INTER) + c*8);
        asm volatile("cp.async.commit_group;" ::: "memory");
    }
    stage(0, 0);
    asm volatile("cp.async.wait_group 1;" ::: "memory");   // Q landed
    __syncthreads();                                       // Q visible

    uint32_t qa[2][4];
    #pragma unroll
    for (int kt = 0; kt < 2; kt++) {
        int row = ib + (lane & 7) + ((lane >> 3) & 1) * 8;
        int col = kt*16 + ((lane >> 4) & 1) * 8;
        ldsm_x4(qa[kt], q_u + (uint32_t)(row*SQB + col)*2);
    }

    float acc[16][4];
    #pragma unroll
    for (int nt = 0; nt < 16; nt++)
        #pragma unroll
        for (int k = 0; k < 4; k++) acc[nt][k] = 0.f;
    float l0 = 0.f, l1 = 0.f;

    for (int jt = 0; jt < 64; jt++) {
        const int s = jt & 1;

        __syncthreads();   // [A] prev iter fully done: buf s^1 and P free
        if (jt < 63) {
            stage(s ^ 1, (jt + 1) * 64);
            asm volatile("cp.async.wait_group 1;" ::: "memory");  // buf s landed
        } else {
            asm volatile("cp.async.wait_group 0;" ::: "memory");
        }
        __syncthreads();   // [V] buf s visible to ALL threads

        const uint32_t k_u = k_u0 + (uint32_t)(s*KBUF)*2;
        const uint32_t v_u = v_u0 + (uint32_t)(s*VBUF)*2;

        // ---- QK^T on this warp's j-half: S[16][32] (log2 units) ----
        float sfr[4][4];
        #pragma unroll
        for (int j8 = 0; j8 < 4; j8++) {
            sfr[j8][0] = sfr[j8][1] = sfr[j8][2] = sfr[j8][3] = 0.f;
            uint32_t kb[4];
            int row = jh + j8*8 + (lane & 7);
            int col = (lane >> 3) * 8;
            ldsm_x4(kb, k_u + (uint32_t)(row*SQB + col)*2);
            mma_bf16(sfr[j8], qa[0], kb[0], kb[1]);
            mma_bf16(sfr[j8], qa[1], kb[2], kb[3]);
        }

        // ---- exp2, accumulate l, store P (bf16) ----
        #pragma unroll
        for (int j8 = 0; j8 < 4; j8++) {
            float p0 = ex2(sfr[j8][0]), p1 = ex2(sfr[j8][1]);
            float p2 = ex2(sfr[j8][2]), p3 = ex2(sfr[j8][3]);
            l0 += p0 + p1;
            l1 += p2 + p3;
            int col = jh + j8*8 + 2*tg;
            *(uint32_t*)(smb + OFFP + (ib + g    )*SPB + col) = packbf(p0, p1);
            *(uint32_t*)(smb + OFFP + (ib + 8 + g)*SPB + col) = packbf(p2, p3);
        }

        // [B] pair barrier: warps {iw, iw+8} both finished their P half.
        asm volatile("bar.sync %0, 64;" :: "r"(1 + iw) : "memory");

        // ---- PV: O[16][128] += P[16][64] x V[64][128] ----
        #pragma unroll
        for (int kt = 0; kt < 4; kt++) {
            uint32_t pa[4];
            {
                int row = ib + (lane & 7) + ((lane >> 3) & 1) * 8;
                int col = kt*16 + ((lane >> 4) & 1) * 8;
                ldsm_x4(pa, p_u + (uint32_t)(row*SPB + col)*2);
            }
            #pragma unroll
            for (int np = 0; np < 8; np++) {
                uint32_t vb[4];
                int row = kt*16 + ((lane >> 3) & 1)*8 + (lane & 7);
                int col = cb + (np*2 + (lane >> 4)) * 8;
                ldsm_x4_t(vb, v_u + (uint32_t)(row*SVB + col)*2);
                mma_bf16(acc[2*np    ], pa, vb[0], vb[1]);
                mma_bf16(acc[2*np + 1], pa, vb[2], vb[3]);
            }
        }
    }

    // ---- combine l across quad lanes + across j-half warps ----
    l0 += __shfl_xor_sync(0xffffffffu, l0, 1);
    l0 += __shfl_xor_sync(0xffffffffu, l0, 2);
    l1 += __shfl_xor_sync(0xffffffffu, l1, 1);
    l1 += __shfl_xor_sync(0xffffffffu, l1, 2);
    if (tg == 0) {
        lsum[(ib + g    )*2 + half] = l0;
        lsum[(ib + 8 + g)*2 + half] = l1;
    }
    __syncthreads();
    float li0 = 1.f / (lsum[(ib + g    )*2] + lsum[(ib + g    )*2 + 1]);
    float li1 = 1.f / (lsum[(ib + 8 + g)*2] + lsum[(ib + 8 + g)*2 + 1]);
    #pragma unroll
    for (int nt = 0; nt < 16; nt++) {
        acc[nt][0] *= li0; acc[nt][1] *= li0;
        acc[nt][2] *= li1; acc[nt][3] *= li1;
    }

    // ---- epilogue: two 64-query halves through smem transpose ----
    const float gmm = gamma_p[0];
    float (*ot)[68] = (float (*)[68])smb;   // [256][68] fp32; lsum is beyond
    for (int h = 0; h < 2; h++) {
        __syncthreads();
        if ((iw >> 2) == h) {
            int il = (ib & 63) + g;   // 0..63 within half
            #pragma unroll
            for (int nt = 0; nt < 16; nt++) {
                int c = cb + nt*8 + 2*tg;
                ot[c  ][il  ] = acc[nt][0];
                ot[c+1][il  ] = acc[nt][1];
                ot[c  ][il+8] = acc[nt][2];
                ot[c+1][il+8] = acc[nt][3];
            }
        }
        __syncthreads();
        {   // 512 threads: c = t>>1, token segment (t&1)*32 (8 float4)
            int c = t >> 1, seg = (t & 1) * 32;
            size_t base = ((size_t)(b*CH + c)) * NTOK + i0 + h*64 + seg;
            const float4* xp = (const float4*)(x + base);
            float4* op = (float4*)(out + base);
            #pragma unroll
            for (int i4 = 0; i4 < 8; i4++) {
                float4 xv = xp[i4];
                float4 r4;
                r4.x = gmm * ot[c][seg + i4*4 + 0] + xv.x;
                r4.y = gmm * ot[c][seg + i4*4 + 1] + xv.y;
                r4.z = gmm * ot[c][seg + i4*4 + 2] + xv.z;
                r4.w = gmm * ot[c][seg + i4*4 + 3] + xv.w;
                op[i4] = r4;
            }
        }
    }
}

// ---------------------------------------------------------------------------
extern "C" void kernel_launch(void* const* d_in, const int* in_sizes, int n_in,
                              void* d_out, int out_size)
{
    const float* x  = (const float*)d_in[0];
    const float* Wq = (const float*)d_in[1];
    const float* bq = (const float*)d_in[2];
    const float* Wk = (const float*)d_in[3];
    const float* bk = (const float*)d_in[4];
    const float* Wv = (const float*)d_in[5];
    const float* bv = (const float*)d_in[6];
    const float* gm = (const float*)d_in[7];
    float* out = (float*)d_out;

    cudaFuncSetAttribute(qkv_kernel,  cudaFuncAttributeMaxDynamicSharedMemorySize, QKV_SMEM_BYTES);
    cudaFuncSetAttribute(attn_kernel, cudaFuncAttributeMaxDynamicSharedMemorySize, ATT_SMEM_BYTES);

    preconv_kernel<<<80 + 2048, 256>>>(x, Wq, bq, Wk, bk, Wv, bv);

    dim3 g1(NTOK / 64, BATCH);
    qkv_kernel<<<g1, 256, QKV_SMEM_BYTES>>>();

    dim3 g2(NTOK / 128, BATCH);
    attn_kernel<<<g2, 512, ATT_SMEM_BYTES>>>(x, gm, out);
}